// round 1
// baseline (speedup 1.0000x reference)
#include <cuda_runtime.h>

// Problem constants (from reference: H=4 heads, D=32 dims)
#define HH 4
#define DD 32
#define MAX_E 1700000
#define MAX_N 65536

// Scratch (no allocations allowed -> __device__ globals)
__device__ float    g_x[(size_t)MAX_E * HH];   // per (edge, head) scaled score
__device__ unsigned g_m[MAX_N * HH];           // per (node, head) max, ordered-uint encoding
__device__ float    g_s[MAX_N * HH];           // per (node, head) sum of exp
__device__ float    g_beta;
__device__ float    g_coef;                    // lam / beta

// float <-> totally-ordered unsigned (monotone map, supports atomicMax on negatives)
__device__ __forceinline__ unsigned f2o(float f) {
    unsigned u = __float_as_uint(f);
    return (u & 0x80000000u) ? ~u : (u | 0x80000000u);
}
__device__ __forceinline__ float o2f(unsigned u) {
    return (u & 0x80000000u) ? __uint_as_float(u ^ 0x80000000u)
                             : __uint_as_float(~u);
}

__global__ void k_scalars(const float* __restrict__ lr, const float* __restrict__ br) {
    float l = lr[0], b = br[0];
    float sp_l = (l > 20.f) ? l : log1pf(expf(l));
    float sp_b = (b > 20.f) ? b : log1pf(expf(b));
    float beta = fminf(sp_b, 10.0f);
    g_beta = beta;
    g_coef = sp_l / beta;
}

__global__ void k_init(float* __restrict__ out, int nh, int gh) {
    int i = blockIdx.x * blockDim.x + threadIdx.x;
    if (i < nh) {
        g_m[i] = 0u;      // f2o of any finite float is > 0, so 0 acts as -inf
        g_s[i] = 0.0f;
    } else if (i < nh + gh) {
        out[i - nh] = 0.0f;
    }
}

// One warp per edge. 32 lanes x float4 = the full 128-float (H*D) node row.
// Lanes [8h, 8h+8) hold head h; butterfly-reduce within each 8-lane group.
__global__ void k_edges(const float* __restrict__ Q, const float* __restrict__ K,
                        const float* __restrict__ a,
                        const int* __restrict__ c2, const int* __restrict__ u2,
                        int E) {
    int w    = (blockIdx.x * blockDim.x + threadIdx.x) >> 5;
    int lane = threadIdx.x & 31;
    if (w >= E) return;

    int c = __ldg(c2 + w);
    int u = __ldg(u2 + w);

    const float4* Qv = (const float4*)Q;
    const float4* Kv = (const float4*)K;
    float4 q = __ldg(Qv + (size_t)c * (HH * DD / 4) + lane);
    float4 k = __ldg(Kv + (size_t)u * (HH * DD / 4) + lane);

    float dot = q.x * k.x + q.y * k.y + q.z * k.z + q.w * k.w;
    dot += __shfl_xor_sync(0xffffffffu, dot, 4);
    dot += __shfl_xor_sync(0xffffffffu, dot, 2);
    dot += __shfl_xor_sync(0xffffffffu, dot, 1);

    if ((lane & 7) == 0) {
        int h = lane >> 3;
        const float inv_scale = 0.17677669529663687f;  // 1/sqrt(32)
        float beta = g_beta;
        float xs = beta * (dot * inv_scale + __ldg(a + h));
        g_x[(size_t)w * HH + h] = xs;
        atomicMax(&g_m[c * HH + h], f2o(xs));
    }
}

// One thread per (edge, head): s[c,h] += exp(x - m[c,h])
__global__ void k_sum(const int* __restrict__ c2, int EH) {
    int idx = blockIdx.x * blockDim.x + threadIdx.x;
    if (idx >= EH) return;
    int e = idx >> 2;           // HH == 4
    int h = idx & 3;
    float xs = g_x[idx];
    int c = __ldg(c2 + e);
    float m = o2f(g_m[c * HH + h]);
    atomicAdd(&g_s[c * HH + h], expf(xs - m));
}

// Per-node lse -> shared G*H bins -> global atomics
__global__ void k_final(const int* __restrict__ batch, float* __restrict__ out,
                        int NH, int gh) {
    extern __shared__ float bins[];
    for (int t = threadIdx.x; t < gh; t += blockDim.x) bins[t] = 0.0f;
    __syncthreads();

    int idx = blockIdx.x * blockDim.x + threadIdx.x;
    if (idx < NH) {
        float s = g_s[idx];
        if (s > 0.0f) {
            int n = idx >> 2;
            int h = idx & 3;
            float m = o2f(g_m[idx]);
            float lse = m + logf(s);
            atomicAdd(&bins[__ldg(batch + n) * HH + h], g_coef * lse);
        }
    }
    __syncthreads();
    for (int t = threadIdx.x; t < gh; t += blockDim.x) {
        float v = bins[t];
        if (v != 0.0f) atomicAdd(out + t, v);
    }
}

extern "C" void kernel_launch(void* const* d_in, const int* in_sizes, int n_in,
                              void* d_out, int out_size) {
    // metadata order: G[0], Q2[1], K2[2], a_2[3], lambda_2_raw[4], beta_2_raw[5],
    //                 c_2[6], u_2[7], batch[8], (num_graphs[9], num_nodes[10])
    const float* Q  = (const float*)d_in[1];
    const float* K  = (const float*)d_in[2];
    const float* a  = (const float*)d_in[3];
    const float* lr = (const float*)d_in[4];
    const float* br = (const float*)d_in[5];
    const int* c2   = (const int*)d_in[6];
    const int* u2   = (const int*)d_in[7];
    const int* bat  = (const int*)d_in[8];

    int E  = in_sizes[6];
    int N  = in_sizes[8];
    int gh = out_size;           // num_graphs * H
    int nh = N * HH;
    int eh = E * HH;
    float* out = (float*)d_out;

    k_scalars<<<1, 1>>>(lr, br);
    k_init<<<(nh + gh + 255) / 256, 256>>>(out, nh, gh);

    long long tot = (long long)E * 32;
    k_edges<<<(unsigned)((tot + 255) / 256), 256>>>(Q, K, a, c2, u2, E);

    k_sum<<<(eh + 255) / 256, 256>>>(c2, eh);

    k_final<<<(nh + 255) / 256, 256, gh * sizeof(float)>>>(bat, out, nh, gh);
}

// round 2
// speedup vs baseline: 1.9552x; 1.9552x over previous
#include <cuda_runtime.h>
#include <cuda_fp16.h>

// Problem constants (H=4 heads, D=32 dims -> 128 floats / row)
#define HH 4
#define DD 32
#define ROW (HH * DD)          // 128
#define MAX_N 65536

// Scratch (__device__ globals; no allocation allowed)
__device__ __half g_qh[(size_t)MAX_N * ROW];   // fp16 copy of Q2
__device__ __half g_kh[(size_t)MAX_N * ROW];   // fp16 copy of K2
__device__ float  g_s[MAX_N * HH];             // per (node, head) sum of exp
__device__ float  g_beta;
__device__ float  g_coef;                      // lam / beta

__global__ void k_scalars(const float* __restrict__ lr, const float* __restrict__ br) {
    float l = lr[0], b = br[0];
    float sp_l = (l > 20.f) ? l : log1pf(expf(l));
    float sp_b = (b > 20.f) ? b : log1pf(expf(b));
    float beta = fminf(sp_b, 10.0f);
    g_beta = beta;
    g_coef = sp_l / beta;
}

__global__ void k_init(float* __restrict__ out, int nh, int gh) {
    int i = blockIdx.x * blockDim.x + threadIdx.x;
    if (i < nh) {
        g_s[i] = 0.0f;
    } else if (i < nh + gh) {
        out[i - nh] = 0.0f;
    }
}

// Streaming fp32 -> fp16 conversion of Q2 and K2. One thread = 4 elements of each.
__global__ void k_convert(const float* __restrict__ Q, const float* __restrict__ K,
                          int nvec /* = N*ROW/4 */) {
    int i = blockIdx.x * blockDim.x + threadIdx.x;
    if (i >= nvec) return;
    float4 q = __ldg((const float4*)Q + i);
    float4 k = __ldg((const float4*)K + i);
    __half2* qo = (__half2*)g_qh;
    __half2* ko = (__half2*)g_kh;
    qo[2 * i]     = __floats2half2_rn(q.x, q.y);
    qo[2 * i + 1] = __floats2half2_rn(q.z, q.w);
    ko[2 * i]     = __floats2half2_rn(k.x, k.y);
    ko[2 * i + 1] = __floats2half2_rn(k.z, k.w);
}

// 16 lanes per edge; each lane loads uint4 = 8 halves of the 128-half row.
// Lanes [4h, 4h+4) within the 16-lane group hold head h (dims 32h..32h+31).
// Butterfly-reduce over 4-lane groups, then atomicAdd(exp(x)) -- single-pass LSE.
__global__ void k_edges(const float* __restrict__ a,
                        const int* __restrict__ c2, const int* __restrict__ u2,
                        int E) {
    int t = blockIdx.x * blockDim.x + threadIdx.x;
    int e = t >> 4;
    if (e >= E) return;
    int l16 = t & 15;

    int c = __ldg(c2 + e);
    int u = __ldg(u2 + e);

    const uint4* Qv = (const uint4*)g_qh;   // 16 uint4 per row
    const uint4* Kv = (const uint4*)g_kh;
    uint4 qr = Qv[(size_t)c * 16 + l16];
    uint4 kr = Kv[(size_t)u * 16 + l16];

    const __half2* qh = (const __half2*)&qr;
    const __half2* kh = (const __half2*)&kr;
    float dot = 0.0f;
#pragma unroll
    for (int j = 0; j < 4; j++) {
        float2 qf = __half22float2(qh[j]);
        float2 kf = __half22float2(kh[j]);
        dot = fmaf(qf.x, kf.x, dot);
        dot = fmaf(qf.y, kf.y, dot);
    }
    // reduce across the 4 lanes of this head (groups aligned mod 4)
    dot += __shfl_xor_sync(0xffffffffu, dot, 2);
    dot += __shfl_xor_sync(0xffffffffu, dot, 1);

    if ((l16 & 3) == 0) {
        int h = l16 >> 2;
        const float inv_scale = 0.17677669529663687f;   // 1/sqrt(32)
        float x = g_beta * (dot * inv_scale + __ldg(a + h));
        atomicAdd(&g_s[c * HH + h], expf(x));
    }
}

// Per-node lse = log(s) -> shared G*H bins -> global atomics
__global__ void k_final(const int* __restrict__ batch, float* __restrict__ out,
                        int NH, int gh) {
    extern __shared__ float bins[];
    for (int t = threadIdx.x; t < gh; t += blockDim.x) bins[t] = 0.0f;
    __syncthreads();

    int idx = blockIdx.x * blockDim.x + threadIdx.x;
    if (idx < NH) {
        float s = g_s[idx];
        if (s > 0.0f) {
            int n = idx >> 2;            // HH == 4
            int h = idx & 3;
            float lse = logf(s);
            atomicAdd(&bins[__ldg(batch + n) * HH + h], g_coef * lse);
        }
    }
    __syncthreads();
    for (int t = threadIdx.x; t < gh; t += blockDim.x) {
        float v = bins[t];
        if (v != 0.0f) atomicAdd(out + t, v);
    }
}

extern "C" void kernel_launch(void* const* d_in, const int* in_sizes, int n_in,
                              void* d_out, int out_size) {
    // metadata order: G[0], Q2[1], K2[2], a_2[3], lambda_2_raw[4], beta_2_raw[5],
    //                 c_2[6], u_2[7], batch[8]
    const float* Q  = (const float*)d_in[1];
    const float* K  = (const float*)d_in[2];
    const float* a  = (const float*)d_in[3];
    const float* lr = (const float*)d_in[4];
    const float* br = (const float*)d_in[5];
    const int* c2   = (const int*)d_in[6];
    const int* u2   = (const int*)d_in[7];
    const int* bat  = (const int*)d_in[8];

    int E  = in_sizes[6];
    int N  = in_sizes[8];
    int gh = out_size;            // num_graphs * H
    int nh = N * HH;
    float* out = (float*)d_out;

    k_scalars<<<1, 1>>>(lr, br);
    k_init<<<(nh + gh + 255) / 256, 256>>>(out, nh, gh);

    int nvec = N * ROW / 4;
    k_convert<<<(nvec + 255) / 256, 256>>>(Q, K, nvec);

    long long tot = (long long)E * 16;
    k_edges<<<(unsigned)((tot + 255) / 256), 256>>>(a, c2, u2, E);

    k_final<<<(nh + 255) / 256, 256, gh * sizeof(float)>>>(bat, out, nh, gh);
}

// round 7
// speedup vs baseline: 1.9732x; 1.0092x over previous
#include <cuda_runtime.h>
#include <cuda_fp16.h>

// Problem constants (H=4 heads, D=32 dims -> 128 halves / node row)
#define HH 4
#define DD 32
#define ROW 128
#define MAX_N 65536

// Scratch (__device__ globals; no allocation allowed)
__device__ __half g_qh[(size_t)MAX_N * ROW];   // fp16 Q premultiplied by beta/sqrt(D)
__device__ __half g_kh[(size_t)MAX_N * ROW];   // fp16 K
__device__ float  g_s[MAX_N * HH];             // per (node, head) sum of exp
__device__ float  g_coef;                      // lam / beta
__device__ float  g_qscale;                    // beta / sqrt(D)
__device__ float  g_eA[HH];                    // exp(beta * a_h)

// Zero accumulators + output; thread (0,0) computes the scalar params.
__global__ void k_init(const float* __restrict__ lr, const float* __restrict__ br,
                       const float* __restrict__ a,
                       float* __restrict__ out, int nh, int gh) {
    int i = blockIdx.x * blockDim.x + threadIdx.x;
    if (i < nh) g_s[i] = 0.0f;
    else if (i < nh + gh) out[i - nh] = 0.0f;
    if (i == 0) {
        float l = lr[0], b = br[0];
        float sp_l = (l > 20.f) ? l : log1pf(expf(l));
        float sp_b = (b > 20.f) ? b : log1pf(expf(b));
        float beta = fminf(sp_b, 10.0f);
        g_coef = sp_l / beta;
        g_qscale = beta * 0.17677669529663687f;   // beta / sqrt(32)
        for (int h = 0; h < HH; h++) g_eA[h] = expf(beta * a[h]);
    }
}

// Streaming fp32 -> fp16; Q gets the beta/scale factor folded in.
__global__ void k_convert(const float* __restrict__ Q, const float* __restrict__ K,
                          int nvec /* = N*ROW/4 */) {
    int i = blockIdx.x * blockDim.x + threadIdx.x;
    if (i >= nvec) return;
    float qs = g_qscale;
    float4 q = __ldg((const float4*)Q + i);
    float4 k = __ldg((const float4*)K + i);
    __half2* qo = (__half2*)g_qh;
    __half2* ko = (__half2*)g_kh;
    qo[2 * i]     = __floats2half2_rn(q.x * qs, q.y * qs);
    qo[2 * i + 1] = __floats2half2_rn(q.z * qs, q.w * qs);
    ko[2 * i]     = __floats2half2_rn(k.x, k.y);
    ko[2 * i + 1] = __floats2half2_rn(k.z, k.w);
}

// 4 lanes per edge: lane handles one head (64B of Q' + 64B of K' = 8 LDG.128, MLP=8).
// HMUL2 products, 2-level HADD2 tree, fp32 final accumulation, single atomic.
__global__ void __launch_bounds__(256) k_edges(const int* __restrict__ c2,
                                               const int* __restrict__ u2, int E) {
    int t = blockIdx.x * blockDim.x + threadIdx.x;
    int e = t >> 2;
    if (e >= E) return;
    int h = t & 3;

    int c = __ldg(c2 + e);
    int u = __ldg(u2 + e);

    const uint4* Qv = (const uint4*)g_qh;   // 16 uint4 per node row
    const uint4* Kv = (const uint4*)g_kh;
    size_t qb = (size_t)c * 16 + h * 4;
    size_t kb = (size_t)u * 16 + h * 4;

    uint4 qr[4], kr[4];
#pragma unroll
    for (int j = 0; j < 4; j++) qr[j] = Qv[qb + j];
#pragma unroll
    for (int j = 0; j < 4; j++) kr[j] = Kv[kb + j];

    float dot = 0.0f;
#pragma unroll
    for (int j = 0; j < 4; j++) {
        const __half2* qa = (const __half2*)&qr[j];
        const __half2* ka = (const __half2*)&kr[j];
        __half2 p0 = __hmul2(qa[0], ka[0]);
        __half2 p1 = __hmul2(qa[1], ka[1]);
        __half2 p2 = __hmul2(qa[2], ka[2]);
        __half2 p3 = __hmul2(qa[3], ka[3]);
        __half2 s = __hadd2(__hadd2(p0, p1), __hadd2(p2, p3));
        float2 f = __half22float2(s);
        dot += f.x + f.y;
    }

    float v = __expf(dot) * g_eA[h];
    atomicAdd(&g_s[c * HH + h], v);
}

// Per-node lse = log(s) -> shared G*H bins -> global atomics
__global__ void k_final(const int* __restrict__ batch, float* __restrict__ out,
                        int NH, int gh) {
    extern __shared__ float bins[];
    for (int t = threadIdx.x; t < gh; t += blockDim.x) bins[t] = 0.0f;
    __syncthreads();

    int idx = blockIdx.x * blockDim.x + threadIdx.x;
    if (idx < NH) {
        float s = g_s[idx];
        if (s > 0.0f) {
            int n = idx >> 2;            // HH == 4
            int h = idx & 3;
            float lse = logf(s);
            atomicAdd(&bins[__ldg(batch + n) * HH + h], g_coef * lse);
        }
    }
    __syncthreads();
    for (int t = threadIdx.x; t < gh; t += blockDim.x) {
        float v = bins[t];
        if (v != 0.0f) atomicAdd(out + t, v);
    }
}

extern "C" void kernel_launch(void* const* d_in, const int* in_sizes, int n_in,
                              void* d_out, int out_size) {
    // metadata order: G[0], Q2[1], K2[2], a_2[3], lambda_2_raw[4], beta_2_raw[5],
    //                 c_2[6], u_2[7], batch[8]
    const float* Q  = (const float*)d_in[1];
    const float* K  = (const float*)d_in[2];
    const float* a  = (const float*)d_in[3];
    const float* lr = (const float*)d_in[4];
    const float* br = (const float*)d_in[5];
    const int* c2   = (const int*)d_in[6];
    const int* u2   = (const int*)d_in[7];
    const int* bat  = (const int*)d_in[8];

    int E  = in_sizes[6];
    int N  = in_sizes[8];
    int gh = out_size;            // num_graphs * H
    int nh = N * HH;
    float* out = (float*)d_out;

    k_init<<<(nh + gh + 255) / 256, 256>>>(lr, br, a, out, nh, gh);

    int nvec = N * ROW / 4;
    k_convert<<<(nvec + 255) / 256, 256>>>(Q, K, nvec);

    long long tot = (long long)E * 4;
    k_edges<<<(unsigned)((tot + 255) / 256), 256>>>(c2, u2, E);

    k_final<<<(nh + 255) / 256, 256, gh * sizeof(float)>>>(bat, out, nh, gh);
}

// round 13
// speedup vs baseline: 2.9917x; 1.5162x over previous
#include <cuda_runtime.h>
#include <cuda_fp16.h>

// Problem constants (H=4 heads, D=32 dims -> 128 halves / node row = 256B)
#define HH 4
#define DD 32
#define ROW 128
#define MAX_N 65536

// Scratch (__device__ globals; no allocation allowed)
__device__ __half g_qh[(size_t)MAX_N * ROW];   // fp16 Q premultiplied by beta/sqrt(D)
__device__ __half g_kh[(size_t)MAX_N * ROW];   // fp16 K
__device__ float  g_s[MAX_N * HH];             // per (node, head) sum of exp
__device__ float  g_coef;                      // lam / beta
__device__ float  g_qscale;                    // beta / sqrt(D)
__device__ float  g_eA[HH];                    // exp(beta * a_h)

// Zero accumulators + output; thread (0,0) computes the scalar params.
__global__ void k_init(const float* __restrict__ lr, const float* __restrict__ br,
                       const float* __restrict__ a,
                       float* __restrict__ out, int nh, int gh) {
    int i = blockIdx.x * blockDim.x + threadIdx.x;
    if (i < nh) g_s[i] = 0.0f;
    else if (i < nh + gh) out[i - nh] = 0.0f;
    if (i == 0) {
        float l = lr[0], b = br[0];
        float sp_l = (l > 20.f) ? l : log1pf(expf(l));
        float sp_b = (b > 20.f) ? b : log1pf(expf(b));
        float beta = fminf(sp_b, 10.0f);
        g_coef = sp_l / beta;
        g_qscale = beta * 0.17677669529663687f;   // beta / sqrt(32)
        for (int h = 0; h < HH; h++) g_eA[h] = expf(beta * a[h]);
    }
}

// Streaming fp32 -> fp16; Q gets the beta/scale factor folded in.
__global__ void k_convert(const float* __restrict__ Q, const float* __restrict__ K,
                          int nvec /* = N*ROW/4 */) {
    int i = blockIdx.x * blockDim.x + threadIdx.x;
    if (i >= nvec) return;
    float qs = g_qscale;
    float4 q = __ldg((const float4*)Q + i);
    float4 k = __ldg((const float4*)K + i);
    __half2* qo = (__half2*)g_qh;
    __half2* ko = (__half2*)g_kh;
    qo[2 * i]     = __floats2half2_rn(q.x * qs, q.y * qs);
    qo[2 * i + 1] = __floats2half2_rn(q.z * qs, q.w * qs);
    ko[2 * i]     = __floats2half2_rn(k.x, k.y);
    ko[2 * i + 1] = __floats2half2_rn(k.z, k.w);
}

// 16 lanes per edge-group, 4 edges per thread.
// Per edge, each lane loads ONE contiguous uint4 (16B) of Q and of K:
// fully coalesced 512B warp transactions, 8 independent loads/thread (MLP=8).
// Lane l16 covers dims [8*l16, 8*l16+8); head h = l16>>2; reduce over 4 lanes.
__global__ void __launch_bounds__(256) k_edges(const int* __restrict__ c2,
                                               const int* __restrict__ u2, int E) {
    int t = blockIdx.x * blockDim.x + threadIdx.x;
    int g = t >> 4;               // edge group: edges [4g, 4g+4)
    int l16 = t & 15;
    int e0 = g * 4;
    if (e0 >= E) return;

    int c[4], u[4];
    if (e0 + 3 < E) {
        int4 cc = __ldg((const int4*)c2 + g);
        int4 uu = __ldg((const int4*)u2 + g);
        c[0] = cc.x; c[1] = cc.y; c[2] = cc.z; c[3] = cc.w;
        u[0] = uu.x; u[1] = uu.y; u[2] = uu.z; u[3] = uu.w;
    } else {
#pragma unroll
        for (int j = 0; j < 4; j++) {
            int e = e0 + j;
            c[j] = (e < E) ? __ldg(c2 + e) : 0;
            u[j] = (e < E) ? __ldg(u2 + e) : 0;
        }
    }

    const uint4* Qv = (const uint4*)g_qh;   // 16 uint4 per node row
    const uint4* Kv = (const uint4*)g_kh;
    uint4 qr[4], kr[4];
#pragma unroll
    for (int j = 0; j < 4; j++) qr[j] = Qv[(size_t)c[j] * 16 + l16];
#pragma unroll
    for (int j = 0; j < 4; j++) kr[j] = Kv[(size_t)u[j] * 16 + l16];

    int h = l16 >> 2;
    float eA = g_eA[h];
    bool leader = (l16 & 3) == 0;

#pragma unroll
    for (int j = 0; j < 4; j++) {
        const __half2* qa = (const __half2*)&qr[j];
        const __half2* ka = (const __half2*)&kr[j];
        __half2 p0 = __hmul2(qa[0], ka[0]);
        __half2 p1 = __hmul2(qa[1], ka[1]);
        __half2 p2 = __hmul2(qa[2], ka[2]);
        __half2 p3 = __hmul2(qa[3], ka[3]);
        __half2 s = __hadd2(__hadd2(p0, p1), __hadd2(p2, p3));
        float2 f = __half22float2(s);
        float dot = f.x + f.y;
        // reduce across the 4 lanes of this head (lane groups aligned mod 4)
        dot += __shfl_xor_sync(0xffffffffu, dot, 2);
        dot += __shfl_xor_sync(0xffffffffu, dot, 1);
        if (leader && (e0 + j) < E) {
            atomicAdd(&g_s[c[j] * HH + h], __expf(dot) * eA);
        }
    }
}

// Per-node lse = log(s) -> shared G*H bins -> global atomics
__global__ void k_final(const int* __restrict__ batch, float* __restrict__ out,
                        int NH, int gh) {
    extern __shared__ float bins[];
    for (int t = threadIdx.x; t < gh; t += blockDim.x) bins[t] = 0.0f;
    __syncthreads();

    int idx = blockIdx.x * blockDim.x + threadIdx.x;
    if (idx < NH) {
        float s = g_s[idx];
        if (s > 0.0f) {
            int n = idx >> 2;            // HH == 4
            int h = idx & 3;
            float lse = logf(s);
            atomicAdd(&bins[__ldg(batch + n) * HH + h], g_coef * lse);
        }
    }
    __syncthreads();
    for (int t = threadIdx.x; t < gh; t += blockDim.x) {
        float v = bins[t];
        if (v != 0.0f) atomicAdd(out + t, v);
    }
}

extern "C" void kernel_launch(void* const* d_in, const int* in_sizes, int n_in,
                              void* d_out, int out_size) {
    // metadata order: G[0], Q2[1], K2[2], a_2[3], lambda_2_raw[4], beta_2_raw[5],
    //                 c_2[6], u_2[7], batch[8]
    const float* Q  = (const float*)d_in[1];
    const float* K  = (const float*)d_in[2];
    const float* a  = (const float*)d_in[3];
    const float* lr = (const float*)d_in[4];
    const float* br = (const float*)d_in[5];
    const int* c2   = (const int*)d_in[6];
    const int* u2   = (const int*)d_in[7];
    const int* bat  = (const int*)d_in[8];

    int E  = in_sizes[6];
    int N  = in_sizes[8];
    int gh = out_size;            // num_graphs * H
    int nh = N * HH;
    float* out = (float*)d_out;

    k_init<<<(nh + gh + 255) / 256, 256>>>(lr, br, a, out, nh, gh);

    int nvec = N * ROW / 4;
    k_convert<<<(nvec + 255) / 256, 256>>>(Q, K, nvec);

    long long groups = (E + 3) / 4;
    long long tot = groups * 16;
    k_edges<<<(unsigned)((tot + 255) / 256), 256>>>(c2, u2, E);

    k_final<<<(nh + 255) / 256, 256, gh * sizeof(float)>>>(bat, out, nh, gh);
}